// round 4
// baseline (speedup 1.0000x reference)
#include <cuda_runtime.h>
#include <cuda_bf16.h>
#include <cstdint>
#include <math.h>

// GELU(x @ W^T + b), split-bf16 (hi/lo, 3-pass) mma.sync HMMA GEMM,
// register-prefetch pipelined. x[8192,512] f32, W[512,512] f32 [out,in], b[512].

#define GN   8192
#define GK   512
#define GOUT 512
#define BM   128
#define BN   64
#define KC   32
#define NIT  (GK / KC)       // 16
#define LDT  40              // smem row stride in bf16 (32 data + 8 pad)

__device__ __forceinline__ uint32_t smem_u32(const void* p) {
    return (uint32_t)__cvta_generic_to_shared(p);
}
__device__ __forceinline__ void ldmx4(uint32_t* r, uint32_t addr) {
    asm volatile("ldmatrix.sync.aligned.m8n8.x4.shared.b16 {%0,%1,%2,%3}, [%4];"
                 : "=r"(r[0]), "=r"(r[1]), "=r"(r[2]), "=r"(r[3]) : "r"(addr));
}
__device__ __forceinline__ void mma16816(float* c, const uint32_t* a, const uint32_t* b) {
    asm volatile(
        "mma.sync.aligned.m16n8k16.row.col.f32.bf16.bf16.f32 "
        "{%0,%1,%2,%3}, {%4,%5,%6,%7}, {%8,%9}, {%0,%1,%2,%3};"
        : "+f"(c[0]), "+f"(c[1]), "+f"(c[2]), "+f"(c[3])
        : "r"(a[0]), "r"(a[1]), "r"(a[2]), "r"(a[3]), "r"(b[0]), "r"(b[1]));
}
__device__ __forceinline__ void split4(float4 v, uint2& hv, uint2& lv) {
    __nv_bfloat16 h0 = __float2bfloat16(v.x);
    __nv_bfloat16 h1 = __float2bfloat16(v.y);
    __nv_bfloat16 h2 = __float2bfloat16(v.z);
    __nv_bfloat16 h3 = __float2bfloat16(v.w);
    __nv_bfloat16 l0 = __float2bfloat16(v.x - __bfloat162float(h0));
    __nv_bfloat16 l1 = __float2bfloat16(v.y - __bfloat162float(h1));
    __nv_bfloat16 l2 = __float2bfloat16(v.z - __bfloat162float(h2));
    __nv_bfloat16 l3 = __float2bfloat16(v.w - __bfloat162float(h3));
    __nv_bfloat162 hp0(h0, h1), hp1(h2, h3), lp0(l0, l1), lp1(l2, l3);
    hv = make_uint2(*reinterpret_cast<uint32_t*>(&hp0), *reinterpret_cast<uint32_t*>(&hp1));
    lv = make_uint2(*reinterpret_cast<uint32_t*>(&lp0), *reinterpret_cast<uint32_t*>(&lp1));
}

__global__ __launch_bounds__(256, 2)
void gemm_bf16x3_gelu(const float* __restrict__ X,
                      const float* __restrict__ W,
                      const float* __restrict__ bias,
                      float* __restrict__ out) {
    __shared__ __nv_bfloat16 Ahi[BM * LDT], Alo[BM * LDT];
    __shared__ __nv_bfloat16 Bhi[BN * LDT], Blo[BN * LDT];

    const int tid = threadIdx.x;
    const int wid = tid >> 5;
    const int lid = tid & 31;
    const int col0 = blockIdx.x * BN;
    const int row0 = blockIdx.y * BM;

    const int m0 = (wid >> 1) * 32;   // 4 warps along M
    const int n0 = (wid & 1) * 32;    // 2 warps along N

    const int lrow  = lid & 15;
    const int lkoff = (lid >> 4) * 8;

    // precomputed ldmatrix base addresses (byte offset kb*2 added per k-step)
    uint32_t aHiA[2], aLoA[2], bHiA[2], bLoA[2];
#pragma unroll
    for (int f = 0; f < 2; f++) {
        aHiA[f] = smem_u32(&Ahi[(m0 + f * 16 + lrow) * LDT]);
        aLoA[f] = smem_u32(&Alo[(m0 + f * 16 + lrow) * LDT]);
        bHiA[f] = smem_u32(&Bhi[(n0 + f * 16 + lrow) * LDT]);
        bLoA[f] = smem_u32(&Blo[(n0 + f * 16 + lrow) * LDT]);
    }

    // A-load indices: 4 float4/thread; B: 2 float4/thread
    const int ar[4] = {(tid + 0) >> 3, (tid + 256) >> 3, (tid + 512) >> 3, (tid + 768) >> 3};
    const int ac4   = tid & 7;

    float acc[2][4][4];
#pragma unroll
    for (int mf = 0; mf < 2; mf++)
#pragma unroll
        for (int nf = 0; nf < 4; nf++)
#pragma unroll
            for (int q = 0; q < 4; q++) acc[mf][nf][q] = 0.0f;

    float4 pa[4], pb[2];

    // ---- prologue: load tile 0, convert, store ----
#pragma unroll
    for (int t = 0; t < 4; t++)
        pa[t] = *reinterpret_cast<const float4*>(X + (size_t)(row0 + ar[t]) * GK + ac4 * 4);
#pragma unroll
    for (int t = 0; t < 2; t++)
        pb[t] = *reinterpret_cast<const float4*>(
            W + (size_t)(col0 + ((tid + t * 256) >> 3)) * GK + ac4 * 4);
#pragma unroll
    for (int t = 0; t < 4; t++) {
        uint2 hv, lv; split4(pa[t], hv, lv);
        *reinterpret_cast<uint2*>(&Ahi[ar[t] * LDT + ac4 * 4]) = hv;
        *reinterpret_cast<uint2*>(&Alo[ar[t] * LDT + ac4 * 4]) = lv;
    }
#pragma unroll
    for (int t = 0; t < 2; t++) {
        const int r = (tid + t * 256) >> 3;
        uint2 hv, lv; split4(pb[t], hv, lv);
        *reinterpret_cast<uint2*>(&Bhi[r * LDT + ac4 * 4]) = hv;
        *reinterpret_cast<uint2*>(&Blo[r * LDT + ac4 * 4]) = lv;
    }
    __syncthreads();

    for (int it = 0; it < NIT; it++) {
        // ---- issue next tile's global loads (latency hidden under MMA) ----
        if (it + 1 < NIT) {
            const int kt = (it + 1) * KC;
#pragma unroll
            for (int t = 0; t < 4; t++)
                pa[t] = *reinterpret_cast<const float4*>(
                    X + (size_t)(row0 + ar[t]) * GK + kt + ac4 * 4);
#pragma unroll
            for (int t = 0; t < 2; t++)
                pb[t] = *reinterpret_cast<const float4*>(
                    W + (size_t)(col0 + ((tid + t * 256) >> 3)) * GK + kt + ac4 * 4);
        }

        // ---- compute current tile: 2 k-steps of 16 ----
#pragma unroll
        for (int ks = 0; ks < 2; ks++) {
            const uint32_t kb = (uint32_t)(ks * 16 + lkoff) * 2;  // bytes
            uint32_t ah[2][4], al[2][4];
#pragma unroll
            for (int mf = 0; mf < 2; mf++) {
                ldmx4(ah[mf], aHiA[mf] + kb);
                ldmx4(al[mf], aLoA[mf] + kb);
            }
            uint32_t bh[4][2], bl[4][2];
#pragma unroll
            for (int f = 0; f < 2; f++) {
                uint32_t r4[4];
                ldmx4(r4, bHiA[f] + kb);
                bh[f * 2][0] = r4[0]; bh[f * 2 + 1][0] = r4[1];
                bh[f * 2][1] = r4[2]; bh[f * 2 + 1][1] = r4[3];
                ldmx4(r4, bLoA[f] + kb);
                bl[f * 2][0] = r4[0]; bl[f * 2 + 1][0] = r4[1];
                bl[f * 2][1] = r4[2]; bl[f * 2 + 1][1] = r4[3];
            }
#pragma unroll
            for (int mf = 0; mf < 2; mf++)
#pragma unroll
                for (int nf = 0; nf < 4; nf++) {
                    mma16816(acc[mf][nf], ah[mf], bh[nf]);
                    mma16816(acc[mf][nf], ah[mf], bl[nf]);
                    mma16816(acc[mf][nf], al[mf], bh[nf]);
                }
        }
        __syncthreads();

        // ---- convert + store next tile ----
        if (it + 1 < NIT) {
#pragma unroll
            for (int t = 0; t < 4; t++) {
                uint2 hv, lv; split4(pa[t], hv, lv);
                *reinterpret_cast<uint2*>(&Ahi[ar[t] * LDT + ac4 * 4]) = hv;
                *reinterpret_cast<uint2*>(&Alo[ar[t] * LDT + ac4 * 4]) = lv;
            }
#pragma unroll
            for (int t = 0; t < 2; t++) {
                const int r = (tid + t * 256) >> 3;
                uint2 hv, lv; split4(pb[t], hv, lv);
                *reinterpret_cast<uint2*>(&Bhi[r * LDT + ac4 * 4]) = hv;
                *reinterpret_cast<uint2*>(&Blo[r * LDT + ac4 * 4]) = lv;
            }
            __syncthreads();
        }
    }

    // ---- epilogue: +bias, exact GELU, store ----
    const float kInvSqrt2 = 0.70710678118654752440f;
    const int lr = lid >> 2;
    const int lc = (lid & 3) * 2;
#pragma unroll
    for (int mf = 0; mf < 2; mf++) {
#pragma unroll
        for (int nf = 0; nf < 4; nf++) {
            const int col = col0 + n0 + nf * 8 + lc;
            const float2 bv = *reinterpret_cast<const float2*>(bias + col);
            const int ra = row0 + m0 + mf * 16 + lr;
#pragma unroll
            for (int half = 0; half < 2; half++) {
                const int r = ra + half * 8;
                float v0 = acc[mf][nf][half * 2 + 0] + bv.x;
                float v1 = acc[mf][nf][half * 2 + 1] + bv.y;
                float g0 = 0.5f * v0 * (1.0f + erff(v0 * kInvSqrt2));
                float g1 = 0.5f * v1 * (1.0f + erff(v1 * kInvSqrt2));
                *reinterpret_cast<float2*>(out + (size_t)r * GOUT + col) =
                    make_float2(g0, g1);
            }
        }
    }
}

extern "C" void kernel_launch(void* const* d_in, const int* in_sizes, int n_in,
                              void* d_out, int out_size) {
    // metadata order: x, adj (unused), W, b, a (unused)
    const float* X    = (const float*)d_in[0];
    const float* W    = (const float*)d_in[2];
    const float* bias = (const float*)d_in[3];
    float* out        = (float*)d_out;

    dim3 grid(GOUT / BN, GN / BM);   // (8, 64) = 512 CTAs
    gemm_bf16x3_gelu<<<grid, 256>>>(X, W, bias, out);
}